// round 12
// baseline (speedup 1.0000x reference)
#include <cuda_runtime.h>
#include <cstdint>

#define NQ    9
#define DIM   512
#define NL    10
#define BATCH 16384
#define NCLS  10

#define BM 128
#define BN 128              // real columns per CTA
#define BKC 32              // K chunk
#define NCHUNK (DIM / BKC)

// ---------------- static scratch ----------------
__device__ float2 g_rot[NL * NQ * 4];
__device__ float2 g_crx[NL * NQ];
__device__ float2 g_UT[DIM * DIM];              // [k][c] complex  (2 MB)
__device__ float  g_Bt[1024 * DIM];             // B frag-major, tf32 (2 MB)
__device__ float  g_Xt[(size_t)BATCH * DIM];    // X frag-major, tf32 (33.5 MB)
__device__ float  g_part[8 * (size_t)BATCH * 10];   // 5.2 MB

// ---------------- helpers ----------------
__device__ __forceinline__ uint32_t smem_u32(const void* p) {
    uint32_t a;
    asm("{ .reg .u64 t; cvta.to.shared.u64 t, %1; cvt.u32.u64 %0, t; }" : "=r"(a) : "l"(p));
    return a;
}
__device__ __forceinline__ void cp16(uint32_t dst, const void* src) {
    asm volatile("cp.async.cg.shared.global [%0], [%1], 16;" :: "r"(dst), "l"(src));
}
__device__ __forceinline__ uint32_t f2tf32(float f) {
    uint32_t u;
    asm("cvt.rna.tf32.f32 %0, %1;" : "=r"(u) : "f"(f));
    return u;
}
__device__ __forceinline__ void mma_tf32(float* d,
                                         uint32_t a0, uint32_t a1, uint32_t a2, uint32_t a3,
                                         uint32_t b0, uint32_t b1) {
    asm volatile("mma.sync.aligned.m16n8k8.row.col.f32.tf32.tf32.f32 "
                 "{%0,%1,%2,%3}, {%4,%5,%6,%7}, {%8,%9}, {%0,%1,%2,%3};"
                 : "+f"(d[0]), "+f"(d[1]), "+f"(d[2]), "+f"(d[3])
                 : "r"(a0), "r"(a1), "r"(a2), "r"(a3), "r"(b0), "r"(b1));
}

// ---------------- kernel 0: gate matrices ----------------
__global__ void gate_prep(const float* __restrict__ rot,
                          const float* __restrict__ crx) {
    int idx = threadIdx.x;
    if (idx >= NL * NQ) return;
    float phi = rot[idx * 3 + 0], theta = rot[idx * 3 + 1], omega = rot[idx * 3 + 2];
    float s, c;  sincosf(0.5f * theta, &s, &c);
    float a = 0.5f * (phi + omega), b = 0.5f * (phi - omega);
    float sa, ca; sincosf(a, &sa, &ca);
    float sb, cb; sincosf(b, &sb, &cb);
    g_rot[idx * 4 + 0] = make_float2( ca * c, -sa * c);
    g_rot[idx * 4 + 1] = make_float2(-cb * s, -sb * s);
    g_rot[idx * 4 + 2] = make_float2( cb * s, -sb * s);
    g_rot[idx * 4 + 3] = make_float2( ca * c,  sa * c);
    float t = crx[idx];
    float st, ct; sincosf(0.5f * t, &st, &ct);
    g_crx[idx] = make_float2(ct, st);
}

// ---------------- kernel 1: build U (validated) ----------------
__global__ __launch_bounds__(256) void build_u() {
    __shared__ float2 psi[DIM];
    int col = blockIdx.x, tid = threadIdx.x;
    psi[tid]       = make_float2(tid == col ? 1.f : 0.f, 0.f);
    psi[tid + 256] = make_float2((tid + 256) == col ? 1.f : 0.f, 0.f);

    for (int n = 0; n < NL; n++) {
        for (int i = 0; i < NQ; i++) {
            int g = n * NQ + i;
            float2 u00 = g_rot[g * 4 + 0], u01 = g_rot[g * 4 + 1];
            float2 u10 = g_rot[g * 4 + 2], u11 = g_rot[g * 4 + 3];
            int k = 8 - i;
            __syncthreads();
            int p  = tid;
            int i0 = ((p >> k) << (k + 1)) | (p & ((1 << k) - 1));
            int i1 = i0 | (1 << k);
            float2 av = psi[i0], bv = psi[i1];
            psi[i0] = make_float2(
                u00.x * av.x - u00.y * av.y + u01.x * bv.x - u01.y * bv.y,
                u00.x * av.y + u00.y * av.x + u01.x * bv.y + u01.y * bv.x);
            psi[i1] = make_float2(
                u10.x * av.x - u10.y * av.y + u11.x * bv.x - u11.y * bv.y,
                u10.x * av.y + u10.y * av.x + u11.x * bv.y + u11.y * bv.x);
        }
        for (int i = 0; i < NQ; i++) {
            int g = n * NQ + i;
            float2 cs = g_crx[g];
            int kc = 8 - i, kt = 8 - ((i + 1) % NQ);
            int lo = kc < kt ? kc : kt;
            int hi = kc < kt ? kt : kc;
            __syncthreads();
            if (tid < 128) {
                int x = tid;
                x = ((x >> lo) << (lo + 1)) | (x & ((1 << lo) - 1));
                x = ((x >> hi) << (hi + 1)) | (x & ((1 << hi) - 1));
                int i0 = x | (1 << kc);
                int i1 = i0 | (1 << kt);
                float2 av = psi[i0], bv = psi[i1];
                psi[i0] = make_float2(cs.x * av.x + cs.y * bv.y,
                                      cs.x * av.y - cs.y * bv.x);
                psi[i1] = make_float2(cs.x * bv.x + cs.y * av.y,
                                      cs.x * bv.y - cs.y * av.x);
            }
        }
    }
    __syncthreads();
    g_UT[col * DIM + tid]       = psi[tid];
    g_UT[col * DIM + tid + 256] = psi[tid + 256];
}

// ---------------- kernel 2a: B -> fragment-major tf32 ----------------
// Bt[n][k] = Br[k][n] with Br = real view of g_UT ([k][1024]).
// Frag float4 at [np][ks][lane] = {Bt[np*16+r][8ks+cg], Bt[np*16+r][8ks+cg+4],
//                                  Bt[np*16+8+r][8ks+cg], Bt[np*16+8+r][8ks+cg+4]}
__global__ __launch_bounds__(256) void conv_b() {
    __shared__ float s[64][17];       // s[kk][n]
    int np = blockIdx.x;              // 0..63
    int n0 = np * 16;
    int t = threadIdx.x;
    float4* Bg = (float4*)g_Bt;
    const float* Br = (const float*)g_UT;

    for (int k0 = 0; k0 < DIM; k0 += 64) {
#pragma unroll
        for (int p = 0; p < 4; p++) {
            int li = t + 256 * p;
            int kk = li >> 4, n = li & 15;
            s[kk][n] = Br[(size_t)(k0 + kk) * 1024 + n0 + n];
        }
        __syncthreads();
        {
            int ksl = t >> 5, lane = t & 31;
            int r = lane >> 2, cg = lane & 3;
            int c = ksl * 8 + cg;
            float4 v;
            v.x = __uint_as_float(f2tf32(s[c][r]));
            v.y = __uint_as_float(f2tf32(s[c + 4][r]));
            v.z = __uint_as_float(f2tf32(s[c][r + 8]));
            v.w = __uint_as_float(f2tf32(s[c + 4][r + 8]));
            Bg[((size_t)np * 64 + (k0 >> 3) + ksl) * 32 + lane] = v;
        }
        __syncthreads();
    }
}

// ---------------- kernel 2b: X -> fragment-major tf32 ----------------
// Frag float4 at [rb][ks][lane] = {A[rb*16+r][8ks+cg], A[rb*16+8+r][8ks+cg],
//                                  A[rb*16+r][8ks+cg+4], A[rb*16+8+r][8ks+cg+4]}
__global__ __launch_bounds__(256) void conv_x(const float* __restrict__ X) {
    __shared__ float s[16][516];
    int rb = blockIdx.x;              // 0..1023
    int m0 = rb * 16;
    int t = threadIdx.x;
    {
        int row = t >> 4, cb = (t & 15) * 32;
        const float4* src = (const float4*)(X + (size_t)(m0 + row) * DIM + cb);
#pragma unroll
        for (int i = 0; i < 8; i++)
            *(float4*)&s[row][cb + 4 * i] = src[i];
    }
    __syncthreads();
    float4* Ag = (float4*)g_Xt;
#pragma unroll
    for (int i = 0; i < 8; i++) {
        int j = t + 256 * i;
        int ks = j >> 5, lane = j & 31;
        int r = lane >> 2, cg = lane & 3;
        int c = ks * 8 + cg;
        float4 v;
        v.x = __uint_as_float(f2tf32(s[r][c]));
        v.y = __uint_as_float(f2tf32(s[r + 8][c]));
        v.z = __uint_as_float(f2tf32(s[r][c + 4]));
        v.w = __uint_as_float(f2tf32(s[r + 8][c + 4]));
        Ag[((size_t)rb * 64 + ks) * 32 + lane] = v;
    }
}

// ---------------- kernel 3: tf32 HMMA GEMM + fused <Z> epilogue ----------------
// smem (float4 units): stage s at s*2048; A [0,1024), B [1024,2048) within stage.
#define SMEM_BYTES 65536

__global__ __launch_bounds__(256, 2) void gemm_tc() {
    extern __shared__ uint4 sm4[];
    uint32_t sb = smem_u32(sm4);
    int tid = threadIdx.x, wid = tid >> 5, lane = tid & 31;
    int bx = blockIdx.x;              // n tile (8)
    int rbBase = blockIdx.y * 8;      // A 16-row blocks
    int npBase = bx * 8;              // B 16-n blocks
    int m0 = blockIdx.y * BM;

    int mw = (wid & 1) * 64;
    int nw = (wid >> 1) * 32;
    int r  = lane >> 2, cg = lane & 3;
    int aB = (wid & 1) * 4;           // rb_local base
    int pB = (wid >> 1) * 2;          // np_local base

    float acc[4][4][4];
#pragma unroll
    for (int i = 0; i < 4; i++)
#pragma unroll
        for (int j = 0; j < 4; j++)
#pragma unroll
            for (int v = 0; v < 4; v++) acc[i][j][v] = 0.f;

    const float4* Ag = (const float4*)g_Xt;
    const float4* Bg = (const float4*)g_Bt;

    // per-thread load slots: j = tid + 256*s -> rb=(j>>7), ksl=(j>>5)&3, ln=j&31
    int rbL[4], ksL[4], lnL[4];
#pragma unroll
    for (int s = 0; s < 4; s++) {
        int j = tid + 256 * s;
        rbL[s] = j >> 7; ksL[s] = (j >> 5) & 3; lnL[s] = j & 31;
    }

    // prefetch chunk 0
#pragma unroll
    for (int s = 0; s < 4; s++) {
        uint32_t so = (uint32_t)((rbL[s] * 128 + ksL[s] * 32 + lnL[s]) * 16);
        cp16(sb + so,
             &Ag[((size_t)(rbBase + rbL[s]) * 64 + ksL[s]) * 32 + lnL[s]]);
        cp16(sb + 16384u + so,
             &Bg[((size_t)(npBase + rbL[s]) * 64 + ksL[s]) * 32 + lnL[s]]);
    }
    asm volatile("cp.async.commit_group;");

    for (int ki = 0; ki < NCHUNK; ki++) {
        if (ki + 1 < NCHUNK) {
            uint32_t bufo = ((ki + 1) & 1) * 32768u;
#pragma unroll
            for (int s = 0; s < 4; s++) {
                uint32_t so = bufo + (uint32_t)((rbL[s] * 128 + ksL[s] * 32 + lnL[s]) * 16);
                cp16(sb + so,
                     &Ag[((size_t)(rbBase + rbL[s]) * 64 + (ki + 1) * 4 + ksL[s]) * 32 + lnL[s]]);
                cp16(sb + 16384u + so,
                     &Bg[((size_t)(npBase + rbL[s]) * 64 + (ki + 1) * 4 + ksL[s]) * 32 + lnL[s]]);
            }
            asm volatile("cp.async.commit_group;");
            asm volatile("cp.async.wait_group 1;");
        } else {
            asm volatile("cp.async.wait_group 0;");
        }
        __syncthreads();

        const uint4* As4 = sm4 + (ki & 1) * 2048;
        const uint4* Bs4 = As4 + 1024;
#pragma unroll
        for (int ks = 0; ks < 4; ks++) {
            uint4 a4[4], b4[2];
#pragma unroll
            for (int i = 0; i < 4; i++)
                a4[i] = As4[(aB + i) * 128 + ks * 32 + lane];
#pragma unroll
            for (int p = 0; p < 2; p++)
                b4[p] = Bs4[(pB + p) * 128 + ks * 32 + lane];
#pragma unroll
            for (int i = 0; i < 4; i++)
#pragma unroll
                for (int p = 0; p < 2; p++) {
                    mma_tf32(acc[i][2 * p],     a4[i].x, a4[i].y, a4[i].z, a4[i].w,
                             b4[p].x, b4[p].y);
                    mma_tf32(acc[i][2 * p + 1], a4[i].x, a4[i].y, a4[i].z, a4[i].w,
                             b4[p].z, b4[p].w);
                }
        }
        __syncthreads();
    }

    // ---- fused epilogue (unchanged from R8) ----
    float* part = (float*)sm4;        // [128][10]
    for (int t = tid; t < 1280; t += 256) part[t] = 0.f;
    __syncthreads();

#pragma unroll
    for (int i = 0; i < 4; i++) {
#pragma unroll
        for (int v = 0; v < 2; v++) {
            int prow = mw + 16 * i + r + 8 * v;
            float loc[10];
#pragma unroll
            for (int q = 0; q < 10; q++) loc[q] = 0.f;
#pragma unroll
            for (int j = 0; j < 4; j++) {
                float re = acc[i][j][2 * v], im = acc[i][j][2 * v + 1];
                float p = fmaf(re, re, im * im);
                int nc = bx * 64 + ((nw + 8 * j) >> 1) + cg;
                loc[9] += p;
#pragma unroll
                for (int q = 0; q < 9; q++)
                    loc[q] += ((nc >> (8 - q)) & 1) ? -p : p;
            }
#pragma unroll
            for (int o = 1; o < 4; o <<= 1)
#pragma unroll
                for (int q = 0; q < 10; q++)
                    loc[q] += __shfl_xor_sync(0xffffffffu, loc[q], o);
            if (cg == 0)
#pragma unroll
                for (int q = 0; q < 10; q++)
                    atomicAdd(&part[prow * 10 + q], loc[q]);
        }
    }
    __syncthreads();
    if (tid < 128) {
        float* dst = g_part + ((size_t)bx * BATCH + m0 + tid) * 10;
#pragma unroll
        for (int q = 0; q < 10; q++) dst[q] = part[tid * 10 + q];
    }
}

// ---------------- kernel 4: sum partials -> head -> log_softmax ----------------
__global__ __launch_bounds__(256) void head_k(const float* __restrict__ fc_w,
                                              const float* __restrict__ fc_b,
                                              float* __restrict__ out) {
    int row = blockIdx.x * 256 + threadIdx.x;
    float a[10];
#pragma unroll
    for (int q = 0; q < 10; q++) a[q] = 0.f;
#pragma unroll
    for (int b = 0; b < 8; b++) {
        const float* p = g_part + ((size_t)b * BATCH + row) * 10;
#pragma unroll
        for (int q = 0; q < 10; q++) a[q] += p[q];
    }
    float inv = 1.0f / a[9];
    float z[9];
#pragma unroll
    for (int q = 0; q < 9; q++) z[q] = a[q] * inv;
    float lg[NCLS]; float mx = -1e30f;
#pragma unroll
    for (int c = 0; c < NCLS; c++) {
        float s = fc_b[c];
#pragma unroll
        for (int q = 0; q < 9; q++) s = fmaf(fc_w[c * 9 + q], z[q], s);
        lg[c] = s; mx = fmaxf(mx, s);
    }
    float se = 0.f;
#pragma unroll
    for (int c = 0; c < NCLS; c++) se += expf(lg[c] - mx);
    float lse = mx + logf(se);
    float* o10 = out + (size_t)row * NCLS;
#pragma unroll
    for (int c = 0; c < NCLS; c++) o10[c] = lg[c] - lse;
}

// ---------------- launch ----------------
extern "C" void kernel_launch(void* const* d_in, const int* in_sizes, int n_in,
                              void* d_out, int out_size) {
    const float* x    = (const float*)d_in[0];
    const float* rot  = (const float*)d_in[1];
    const float* crx  = (const float*)d_in[2];
    const float* fc_w = (const float*)d_in[3];
    const float* fc_b = (const float*)d_in[4];
    float* out = (float*)d_out;

    static bool attr_set = false;
    if (!attr_set) {
        cudaFuncSetAttribute(gemm_tc, cudaFuncAttributeMaxDynamicSharedMemorySize,
                             SMEM_BYTES);
        attr_set = true;
    }

    gate_prep<<<1, 128>>>(rot, crx);
    build_u<<<DIM, 256>>>();
    conv_b<<<64, 256>>>();
    conv_x<<<BATCH / 16, 256>>>(x);
    gemm_tc<<<dim3(1024 / BN, BATCH / BM), 256, SMEM_BYTES>>>();
    head_k<<<BATCH / 256, 256>>>(fc_w, fc_b, out);
    (void)in_sizes; (void)n_in; (void)out_size;
}

// round 13
// speedup vs baseline: 1.0034x; 1.0034x over previous
#include <cuda_runtime.h>
#include <cstdint>

#define NQ    9
#define DIM   512
#define NL    10
#define BATCH 16384
#define NCLS  10

#define BM 128
#define BN 128              // real columns per CTA
#define BKC 32              // K chunk
#define NCHUNK (DIM / BKC)

// ---------------- static scratch ----------------
__device__ float2 g_rot[NL * NQ * 4];
__device__ float2 g_crx[NL * NQ];
__device__ float2 g_UT[DIM * DIM];              // [k][c] complex  (2 MB)
__device__ float  g_Bt[1024 * DIM];             // B frag-major, tf32 (2 MB)
__device__ float  g_Xt[(size_t)BATCH * DIM];    // X frag-major, tf32 (33.5 MB)
__device__ float  g_part[8 * (size_t)BATCH * 10];   // 5.2 MB

// ---------------- helpers ----------------
__device__ __forceinline__ uint32_t smem_u32(const void* p) {
    uint32_t a;
    asm("{ .reg .u64 t; cvta.to.shared.u64 t, %1; cvt.u32.u64 %0, t; }" : "=r"(a) : "l"(p));
    return a;
}
__device__ __forceinline__ void cp16(uint32_t dst, const void* src) {
    asm volatile("cp.async.cg.shared.global [%0], [%1], 16;" :: "r"(dst), "l"(src));
}
__device__ __forceinline__ uint32_t f2tf32(float f) {
    uint32_t u;
    asm("cvt.rna.tf32.f32 %0, %1;" : "=r"(u) : "f"(f));
    return u;
}
__device__ __forceinline__ void mma_tf32(float* d,
                                         uint32_t a0, uint32_t a1, uint32_t a2, uint32_t a3,
                                         uint32_t b0, uint32_t b1) {
    asm volatile("mma.sync.aligned.m16n8k8.row.col.f32.tf32.tf32.f32 "
                 "{%0,%1,%2,%3}, {%4,%5,%6,%7}, {%8,%9}, {%0,%1,%2,%3};"
                 : "+f"(d[0]), "+f"(d[1]), "+f"(d[2]), "+f"(d[3])
                 : "r"(a0), "r"(a1), "r"(a2), "r"(a3), "r"(b0), "r"(b1));
}

// ---------------- kernel 0: gate matrices ----------------
__global__ void gate_prep(const float* __restrict__ rot,
                          const float* __restrict__ crx) {
    int idx = threadIdx.x;
    if (idx >= NL * NQ) return;
    float phi = rot[idx * 3 + 0], theta = rot[idx * 3 + 1], omega = rot[idx * 3 + 2];
    float s, c;  sincosf(0.5f * theta, &s, &c);
    float a = 0.5f * (phi + omega), b = 0.5f * (phi - omega);
    float sa, ca; sincosf(a, &sa, &ca);
    float sb, cb; sincosf(b, &sb, &cb);
    g_rot[idx * 4 + 0] = make_float2( ca * c, -sa * c);
    g_rot[idx * 4 + 1] = make_float2(-cb * s, -sb * s);
    g_rot[idx * 4 + 2] = make_float2( cb * s, -sb * s);
    g_rot[idx * 4 + 3] = make_float2( ca * c,  sa * c);
    float t = crx[idx];
    float st, ct; sincosf(0.5f * t, &st, &ct);
    g_crx[idx] = make_float2(ct, st);
}

// ---------------- kernel 1: build U (validated) ----------------
__global__ __launch_bounds__(256) void build_u() {
    __shared__ float2 psi[DIM];
    int col = blockIdx.x, tid = threadIdx.x;
    psi[tid]       = make_float2(tid == col ? 1.f : 0.f, 0.f);
    psi[tid + 256] = make_float2((tid + 256) == col ? 1.f : 0.f, 0.f);

    for (int n = 0; n < NL; n++) {
        for (int i = 0; i < NQ; i++) {
            int g = n * NQ + i;
            float2 u00 = g_rot[g * 4 + 0], u01 = g_rot[g * 4 + 1];
            float2 u10 = g_rot[g * 4 + 2], u11 = g_rot[g * 4 + 3];
            int k = 8 - i;
            __syncthreads();
            int p  = tid;
            int i0 = ((p >> k) << (k + 1)) | (p & ((1 << k) - 1));
            int i1 = i0 | (1 << k);
            float2 av = psi[i0], bv = psi[i1];
            psi[i0] = make_float2(
                u00.x * av.x - u00.y * av.y + u01.x * bv.x - u01.y * bv.y,
                u00.x * av.y + u00.y * av.x + u01.x * bv.y + u01.y * bv.x);
            psi[i1] = make_float2(
                u10.x * av.x - u10.y * av.y + u11.x * bv.x - u11.y * bv.y,
                u10.x * av.y + u10.y * av.x + u11.x * bv.y + u11.y * bv.x);
        }
        for (int i = 0; i < NQ; i++) {
            int g = n * NQ + i;
            float2 cs = g_crx[g];
            int kc = 8 - i, kt = 8 - ((i + 1) % NQ);
            int lo = kc < kt ? kc : kt;
            int hi = kc < kt ? kt : kc;
            __syncthreads();
            if (tid < 128) {
                int x = tid;
                x = ((x >> lo) << (lo + 1)) | (x & ((1 << lo) - 1));
                x = ((x >> hi) << (hi + 1)) | (x & ((1 << hi) - 1));
                int i0 = x | (1 << kc);
                int i1 = i0 | (1 << kt);
                float2 av = psi[i0], bv = psi[i1];
                psi[i0] = make_float2(cs.x * av.x + cs.y * bv.y,
                                      cs.x * av.y - cs.y * bv.x);
                psi[i1] = make_float2(cs.x * bv.x + cs.y * av.y,
                                      cs.x * bv.y - cs.y * av.x);
            }
        }
    }
    __syncthreads();
    g_UT[col * DIM + tid]       = psi[tid];
    g_UT[col * DIM + tid + 256] = psi[tid + 256];
}

// ---------------- kernel 2a: B -> fragment-major tf32 ----------------
// Bt[n][k] = Br[k][n] with Br = real view of g_UT ([k][1024]).
// Frag float4 at [np][ks][lane] = {Bt[np*16+r][8ks+cg], Bt[np*16+r][8ks+cg+4],
//                                  Bt[np*16+8+r][8ks+cg], Bt[np*16+8+r][8ks+cg+4]}
__global__ __launch_bounds__(256) void conv_b() {
    __shared__ float s[64][17];       // s[kk][n]
    int np = blockIdx.x;              // 0..63
    int n0 = np * 16;
    int t = threadIdx.x;
    float4* Bg = (float4*)g_Bt;
    const float* Br = (const float*)g_UT;

    for (int k0 = 0; k0 < DIM; k0 += 64) {
#pragma unroll
        for (int p = 0; p < 4; p++) {
            int li = t + 256 * p;
            int kk = li >> 4, n = li & 15;
            s[kk][n] = Br[(size_t)(k0 + kk) * 1024 + n0 + n];
        }
        __syncthreads();
        {
            int ksl = t >> 5, lane = t & 31;
            int r = lane >> 2, cg = lane & 3;
            int c = ksl * 8 + cg;
            float4 v;
            v.x = __uint_as_float(f2tf32(s[c][r]));
            v.y = __uint_as_float(f2tf32(s[c + 4][r]));
            v.z = __uint_as_float(f2tf32(s[c][r + 8]));
            v.w = __uint_as_float(f2tf32(s[c + 4][r + 8]));
            Bg[((size_t)np * 64 + (k0 >> 3) + ksl) * 32 + lane] = v;
        }
        __syncthreads();
    }
}

// ---------------- kernel 2b: X -> fragment-major tf32 ----------------
// Frag float4 at [rb][ks][lane] = {A[rb*16+r][8ks+cg], A[rb*16+8+r][8ks+cg],
//                                  A[rb*16+r][8ks+cg+4], A[rb*16+8+r][8ks+cg+4]}
__global__ __launch_bounds__(256) void conv_x(const float* __restrict__ X) {
    __shared__ float s[16][516];
    int rb = blockIdx.x;              // 0..1023
    int m0 = rb * 16;
    int t = threadIdx.x;
    {
        int row = t >> 4, cb = (t & 15) * 32;
        const float4* src = (const float4*)(X + (size_t)(m0 + row) * DIM + cb);
#pragma unroll
        for (int i = 0; i < 8; i++)
            *(float4*)&s[row][cb + 4 * i] = src[i];
    }
    __syncthreads();
    float4* Ag = (float4*)g_Xt;
#pragma unroll
    for (int i = 0; i < 8; i++) {
        int j = t + 256 * i;
        int ks = j >> 5, lane = j & 31;
        int r = lane >> 2, cg = lane & 3;
        int c = ks * 8 + cg;
        float4 v;
        v.x = __uint_as_float(f2tf32(s[r][c]));
        v.y = __uint_as_float(f2tf32(s[r + 8][c]));
        v.z = __uint_as_float(f2tf32(s[r][c + 4]));
        v.w = __uint_as_float(f2tf32(s[r + 8][c + 4]));
        Ag[((size_t)rb * 64 + ks) * 32 + lane] = v;
    }
}

// ---------------- kernel 3: tf32 HMMA GEMM + fused <Z> epilogue ----------------
// smem (float4 units): stage s at s*2048; A [0,1024), B [1024,2048) within stage.
#define SMEM_BYTES 65536

__global__ __launch_bounds__(256, 2) void gemm_tc() {
    extern __shared__ uint4 sm4[];
    uint32_t sb = smem_u32(sm4);
    int tid = threadIdx.x, wid = tid >> 5, lane = tid & 31;
    int bx = blockIdx.x;              // n tile (8)
    int rbBase = blockIdx.y * 8;      // A 16-row blocks
    int npBase = bx * 8;              // B 16-n blocks
    int m0 = blockIdx.y * BM;

    int mw = (wid & 1) * 64;
    int nw = (wid >> 1) * 32;
    int r  = lane >> 2, cg = lane & 3;
    int aB = (wid & 1) * 4;           // rb_local base
    int pB = (wid >> 1) * 2;          // np_local base

    float acc[4][4][4];
#pragma unroll
    for (int i = 0; i < 4; i++)
#pragma unroll
        for (int j = 0; j < 4; j++)
#pragma unroll
            for (int v = 0; v < 4; v++) acc[i][j][v] = 0.f;

    const float4* Ag = (const float4*)g_Xt;
    const float4* Bg = (const float4*)g_Bt;

    // per-thread load slots: j = tid + 256*s -> rb=(j>>7), ksl=(j>>5)&3, ln=j&31
    int rbL[4], ksL[4], lnL[4];
#pragma unroll
    for (int s = 0; s < 4; s++) {
        int j = tid + 256 * s;
        rbL[s] = j >> 7; ksL[s] = (j >> 5) & 3; lnL[s] = j & 31;
    }

    // prefetch chunk 0
#pragma unroll
    for (int s = 0; s < 4; s++) {
        uint32_t so = (uint32_t)((rbL[s] * 128 + ksL[s] * 32 + lnL[s]) * 16);
        cp16(sb + so,
             &Ag[((size_t)(rbBase + rbL[s]) * 64 + ksL[s]) * 32 + lnL[s]]);
        cp16(sb + 16384u + so,
             &Bg[((size_t)(npBase + rbL[s]) * 64 + ksL[s]) * 32 + lnL[s]]);
    }
    asm volatile("cp.async.commit_group;");

    for (int ki = 0; ki < NCHUNK; ki++) {
        if (ki + 1 < NCHUNK) {
            uint32_t bufo = ((ki + 1) & 1) * 32768u;
#pragma unroll
            for (int s = 0; s < 4; s++) {
                uint32_t so = bufo + (uint32_t)((rbL[s] * 128 + ksL[s] * 32 + lnL[s]) * 16);
                cp16(sb + so,
                     &Ag[((size_t)(rbBase + rbL[s]) * 64 + (ki + 1) * 4 + ksL[s]) * 32 + lnL[s]]);
                cp16(sb + 16384u + so,
                     &Bg[((size_t)(npBase + rbL[s]) * 64 + (ki + 1) * 4 + ksL[s]) * 32 + lnL[s]]);
            }
            asm volatile("cp.async.commit_group;");
            asm volatile("cp.async.wait_group 1;");
        } else {
            asm volatile("cp.async.wait_group 0;");
        }
        __syncthreads();

        const uint4* As4 = sm4 + (ki & 1) * 2048;
        const uint4* Bs4 = As4 + 1024;
#pragma unroll
        for (int ks = 0; ks < 4; ks++) {
            uint4 a4[4], b4[2];
#pragma unroll
            for (int i = 0; i < 4; i++)
                a4[i] = As4[(aB + i) * 128 + ks * 32 + lane];
#pragma unroll
            for (int p = 0; p < 2; p++)
                b4[p] = Bs4[(pB + p) * 128 + ks * 32 + lane];
#pragma unroll
            for (int i = 0; i < 4; i++)
#pragma unroll
                for (int p = 0; p < 2; p++) {
                    mma_tf32(acc[i][2 * p],     a4[i].x, a4[i].y, a4[i].z, a4[i].w,
                             b4[p].x, b4[p].y);
                    mma_tf32(acc[i][2 * p + 1], a4[i].x, a4[i].y, a4[i].z, a4[i].w,
                             b4[p].z, b4[p].w);
                }
        }
        __syncthreads();
    }

    // ---- fused epilogue (unchanged from R8) ----
    float* part = (float*)sm4;        // [128][10]
    for (int t = tid; t < 1280; t += 256) part[t] = 0.f;
    __syncthreads();

#pragma unroll
    for (int i = 0; i < 4; i++) {
#pragma unroll
        for (int v = 0; v < 2; v++) {
            int prow = mw + 16 * i + r + 8 * v;
            float loc[10];
#pragma unroll
            for (int q = 0; q < 10; q++) loc[q] = 0.f;
#pragma unroll
            for (int j = 0; j < 4; j++) {
                float re = acc[i][j][2 * v], im = acc[i][j][2 * v + 1];
                float p = fmaf(re, re, im * im);
                int nc = bx * 64 + ((nw + 8 * j) >> 1) + cg;
                loc[9] += p;
#pragma unroll
                for (int q = 0; q < 9; q++)
                    loc[q] += ((nc >> (8 - q)) & 1) ? -p : p;
            }
#pragma unroll
            for (int o = 1; o < 4; o <<= 1)
#pragma unroll
                for (int q = 0; q < 10; q++)
                    loc[q] += __shfl_xor_sync(0xffffffffu, loc[q], o);
            if (cg == 0)
#pragma unroll
                for (int q = 0; q < 10; q++)
                    atomicAdd(&part[prow * 10 + q], loc[q]);
        }
    }
    __syncthreads();
    if (tid < 128) {
        float* dst = g_part + ((size_t)bx * BATCH + m0 + tid) * 10;
#pragma unroll
        for (int q = 0; q < 10; q++) dst[q] = part[tid * 10 + q];
    }
}

// ---------------- kernel 4: sum partials -> head -> log_softmax ----------------
__global__ __launch_bounds__(256) void head_k(const float* __restrict__ fc_w,
                                              const float* __restrict__ fc_b,
                                              float* __restrict__ out) {
    int row = blockIdx.x * 256 + threadIdx.x;
    float a[10];
#pragma unroll
    for (int q = 0; q < 10; q++) a[q] = 0.f;
#pragma unroll
    for (int b = 0; b < 8; b++) {
        const float* p = g_part + ((size_t)b * BATCH + row) * 10;
#pragma unroll
        for (int q = 0; q < 10; q++) a[q] += p[q];
    }
    float inv = 1.0f / a[9];
    float z[9];
#pragma unroll
    for (int q = 0; q < 9; q++) z[q] = a[q] * inv;
    float lg[NCLS]; float mx = -1e30f;
#pragma unroll
    for (int c = 0; c < NCLS; c++) {
        float s = fc_b[c];
#pragma unroll
        for (int q = 0; q < 9; q++) s = fmaf(fc_w[c * 9 + q], z[q], s);
        lg[c] = s; mx = fmaxf(mx, s);
    }
    float se = 0.f;
#pragma unroll
    for (int c = 0; c < NCLS; c++) se += expf(lg[c] - mx);
    float lse = mx + logf(se);
    float* o10 = out + (size_t)row * NCLS;
#pragma unroll
    for (int c = 0; c < NCLS; c++) o10[c] = lg[c] - lse;
}

// ---------------- launch ----------------
extern "C" void kernel_launch(void* const* d_in, const int* in_sizes, int n_in,
                              void* d_out, int out_size) {
    const float* x    = (const float*)d_in[0];
    const float* rot  = (const float*)d_in[1];
    const float* crx  = (const float*)d_in[2];
    const float* fc_w = (const float*)d_in[3];
    const float* fc_b = (const float*)d_in[4];
    float* out = (float*)d_out;

    static bool attr_set = false;
    if (!attr_set) {
        cudaFuncSetAttribute(gemm_tc, cudaFuncAttributeMaxDynamicSharedMemorySize,
                             SMEM_BYTES);
        attr_set = true;
    }

    gate_prep<<<1, 128>>>(rot, crx);
    build_u<<<DIM, 256>>>();
    conv_b<<<64, 256>>>();
    conv_x<<<BATCH / 16, 256>>>(x);
    gemm_tc<<<dim3(1024 / BN, BATCH / BM), 256, SMEM_BYTES>>>();
    head_k<<<BATCH / 256, 256>>>(fc_w, fc_b, out);
    (void)in_sizes; (void)n_in; (void)out_size;
}